// round 3
// baseline (speedup 1.0000x reference)
#include <cuda_runtime.h>

// Problem constants (validated rel_err=0.0 in R1/R2): W=400, H=352, D=5
#define BB 2
#define CC 64
#define NN (64 * 2048)      // RH*RW = 131072 points per batch
#define WW 400
#define HH 352
#define DD 5
#define DWH (DD * WW * HH)  // 704000 cells per batch

// Scratch
__device__ int   g_winner[BB * DWH];          // winner point-index per cell, -1 = empty
__device__ float g_feat_t[(size_t)BB * NN * CC];  // transposed features (B, N, C), 67 MB

// ---------------------------------------------------------------------------
// Pass 1: resolve winners (last point index wins, matching XLA scatter order)
// ---------------------------------------------------------------------------
__global__ void scatter_winner_kernel(const float* __restrict__ xyz) {
    int t = blockIdx.x * blockDim.x + threadIdx.x;
    if (t >= BB * NN) return;
    int b = t >> 17;          // NN = 2^17
    int n = t & (NN - 1);

    const float xp = xyz[(b * 3 + 0) * NN + n];
    const float yp = xyz[(b * 3 + 1) * NN + n];
    const float zp = xyz[(b * 3 + 2) * NN + n];

    if (!(zp >= -3.0f && zp < 1.0f)) return;
    int zbin = (int)floorf(__fdiv_rn(zp + 3.0f, 0.8f));
    if (zbin < 0 || zbin >= DD) return;

    int xi = (int)__fdiv_rn(-yp, 0.2f) + 200;   // x_img = trunc(-y/0.2)+200
    xi = min(max(xi, 0), WW - 1);
    int yi = (int)__fdiv_rn(-xp, 0.2f) + 352;   // y_img = trunc(-x/0.2)+352
    yi = min(max(yi, 0), HH - 1);

    int cell = (zbin * WW + (WW - 1 - xi)) * HH + (HH - 1 - yi);
    atomicMax(&g_winner[b * DWH + cell], n);
}

// ---------------------------------------------------------------------------
// Pass 2: coalesced transpose (B, C, N) -> (B, N, C)
// 32x32 tiles in smem; both gmem accesses fully coalesced.
// ---------------------------------------------------------------------------
__global__ void __launch_bounds__(256) transpose_kernel(const float* __restrict__ feat) {
    __shared__ float tile[32][33];
    const int b  = blockIdx.z;
    const int c0 = blockIdx.y * 32;
    const int n0 = blockIdx.x * 32;
    const int tx = threadIdx.x;        // 0..31
    const int ty = threadIdx.y;        // 0..7

    const float* src = feat + ((size_t)b * CC + c0) * NN + n0;
    #pragma unroll
    for (int j = 0; j < 4; j++) {
        tile[ty + j * 8][tx] = src[(size_t)(ty + j * 8) * NN + tx];
    }
    __syncthreads();

    float* dst = g_feat_t + ((size_t)b * NN + n0) * CC + c0;
    #pragma unroll
    for (int j = 0; j < 4; j++) {
        dst[(size_t)(ty + j * 8) * CC + tx] = tile[tx][ty + j * 8];
    }
}

// ---------------------------------------------------------------------------
// Pass 3: writer. One thread per cell. Winner loaded once; the 64 channel
// values are 256B contiguous in g_feat_t (16 float4 loads, 100% sector use).
// Output stores streamed (__stcs) to keep g_feat_t L2-resident.
// ---------------------------------------------------------------------------
__global__ void __launch_bounds__(256) write_bev_kernel(float* __restrict__ out) {
    const int b    = blockIdx.y;
    const int cell = blockIdx.x * 256 + threadIdx.x;   // DWH % 256 == 0

    const int w = g_winner[b * DWH + cell];
    float* ob = out + (size_t)b * CC * DWH + cell;

    if (w >= 0) {
        const float4* src =
            reinterpret_cast<const float4*>(g_feat_t + ((size_t)b * NN + w) * CC);
        #pragma unroll
        for (int q = 0; q < 16; q++) {
            float4 v = __ldg(src + q);
            __stcs(ob + (size_t)(q * 4 + 0) * DWH, v.x);
            __stcs(ob + (size_t)(q * 4 + 1) * DWH, v.y);
            __stcs(ob + (size_t)(q * 4 + 2) * DWH, v.z);
            __stcs(ob + (size_t)(q * 4 + 3) * DWH, v.w);
        }
    } else {
        #pragma unroll
        for (int c = 0; c < CC; c++) {
            __stcs(ob + (size_t)c * DWH, 0.0f);
        }
    }
}

extern "C" void kernel_launch(void* const* d_in, const int* in_sizes, int n_in,
                              void* d_out, int out_size) {
    const float* range_res = (const float*)d_in[0];   // (B, C, RH, RW)
    const float* xyz       = (const float*)d_in[1];   // (B, 3, RH, RW)
    float* out = (float*)d_out;                       // (B, C, D, W, H)

    static int* winner_ptr = nullptr;
    if (!winner_ptr) cudaGetSymbolAddress((void**)&winner_ptr, g_winner);

    // 1) winner map := -1 (0xFF per byte) — memset node, capturable
    cudaMemsetAsync(winner_ptr, 0xFF, sizeof(int) * (size_t)BB * DWH);

    // 2) resolve winners
    scatter_winner_kernel<<<(BB * NN + 255) / 256, 256>>>(xyz);

    // 3) transpose features to (B, N, C)
    {
        dim3 grid(NN / 32, CC / 32, BB);   // (4096, 2, 2)
        dim3 block(32, 8);
        transpose_kernel<<<grid, block>>>(range_res);
    }

    // 4) write BEV output
    {
        dim3 grid(DWH / 256, BB);          // (2750, 2)
        write_bev_kernel<<<grid, 256>>>(out);
    }
}

// round 4
// speedup vs baseline: 1.8551x; 1.8551x over previous
#include <cuda_runtime.h>

// Problem constants (validated rel_err=0.0): W=400, H=352, D=5
#define BB 2
#define CC 64
#define NN (64 * 2048)      // RH*RW = 131072 points per batch
#define WW 400
#define HH 352
#define DD 5
#define DWH (DD * WW * HH)  // 704000 cells per batch
#define NG  (DWH / 4)       // 176000 cell-groups (4 cells each) per batch

// Scratch
__device__ int   g_winner[BB * DWH];               // winner point idx per cell, -1 = empty
__device__ float g_feat_t[(size_t)BB * NN * CC];   // transposed features (B, N, C)

// ---------------------------------------------------------------------------
// Pass 1: resolve winners (last point index wins = XLA scatter order)
// ---------------------------------------------------------------------------
__global__ void scatter_winner_kernel(const float* __restrict__ xyz) {
    int t = blockIdx.x * blockDim.x + threadIdx.x;
    if (t >= BB * NN) return;
    int b = t >> 17;          // NN = 2^17
    int n = t & (NN - 1);

    const float xp = xyz[(b * 3 + 0) * NN + n];
    const float yp = xyz[(b * 3 + 1) * NN + n];
    const float zp = xyz[(b * 3 + 2) * NN + n];

    if (!(zp >= -3.0f && zp < 1.0f)) return;
    int zbin = (int)floorf(__fdiv_rn(zp + 3.0f, 0.8f));
    if (zbin < 0 || zbin >= DD) return;

    int xi = (int)__fdiv_rn(-yp, 0.2f) + 200;   // x_img
    xi = min(max(xi, 0), WW - 1);
    int yi = (int)__fdiv_rn(-xp, 0.2f) + 352;   // y_img
    yi = min(max(yi, 0), HH - 1);

    int cell = (zbin * WW + (WW - 1 - xi)) * HH + (HH - 1 - yi);
    atomicMax(&g_winner[b * DWH + cell], n);
}

// ---------------------------------------------------------------------------
// Pass 2: coalesced transpose (B, C, N) -> (B, N, C)
// ---------------------------------------------------------------------------
__global__ void __launch_bounds__(256) transpose_kernel(const float* __restrict__ feat) {
    __shared__ float tile[32][33];
    const int b  = blockIdx.z;
    const int c0 = blockIdx.y * 32;
    const int n0 = blockIdx.x * 32;
    const int tx = threadIdx.x;        // 0..31
    const int ty = threadIdx.y;        // 0..7

    const float* src = feat + ((size_t)b * CC + c0) * NN + n0;
    #pragma unroll
    for (int j = 0; j < 4; j++)
        tile[ty + j * 8][tx] = src[(size_t)(ty + j * 8) * NN + tx];
    __syncthreads();

    float* dst = g_feat_t + ((size_t)b * NN + n0) * CC + c0;
    #pragma unroll
    for (int j = 0; j < 4; j++)
        dst[(size_t)(ty + j * 8) * CC + tx] = tile[tx][ty + j * 8];
}

// ---------------------------------------------------------------------------
// Pass 3: writer. Thread = (4 consecutive cells, 16 channels).
//  - winner int4 loaded once per thread (coalesced)
//  - gathers: 4 x 64B dense rows from g_feat_t (100% sector utilization)
//  - stores: 16 float4, per-warp 512B contiguous (all lanes same channel grp)
// ---------------------------------------------------------------------------
__device__ __forceinline__ float f4c(const float4& f, int k) {
    return k == 0 ? f.x : k == 1 ? f.y : k == 2 ? f.z : f.w;
}

__global__ void __launch_bounds__(128) write_bev_kernel(float* __restrict__ out) {
    const int g = blockIdx.x * 128 + threadIdx.x;   // cell-group
    if (g >= NG) return;
    const int cg = blockIdx.y;                      // channel group: channels cg*16..+15
    const int b  = blockIdx.z;
    const int cell0 = g * 4;

    const int4 w = *reinterpret_cast<const int4*>(&g_winner[b * DWH + cell0]);
    const int ws[4] = {w.x, w.y, w.z, w.w};

    const float* fb = g_feat_t + (size_t)b * NN * CC + cg * 16;

    float4 v[4][4];   // [cell-in-group][channel quad]
    #pragma unroll
    for (int i = 0; i < 4; i++) {
        if (ws[i] >= 0) {
            const float4* src = reinterpret_cast<const float4*>(fb + (size_t)ws[i] * CC);
            v[i][0] = __ldg(src + 0);
            v[i][1] = __ldg(src + 1);
            v[i][2] = __ldg(src + 2);
            v[i][3] = __ldg(src + 3);
        } else {
            v[i][0] = v[i][1] = v[i][2] = v[i][3] = make_float4(0.f, 0.f, 0.f, 0.f);
        }
    }

    float* ob = out + ((size_t)b * CC + cg * 16) * DWH + cell0;
    #pragma unroll
    for (int c = 0; c < 16; c++) {
        const int q = c >> 2, k = c & 3;
        float4 r;
        r.x = f4c(v[0][q], k);
        r.y = f4c(v[1][q], k);
        r.z = f4c(v[2][q], k);
        r.w = f4c(v[3][q], k);
        *reinterpret_cast<float4*>(ob + (size_t)c * DWH) = r;
    }
}

extern "C" void kernel_launch(void* const* d_in, const int* in_sizes, int n_in,
                              void* d_out, int out_size) {
    const float* range_res = (const float*)d_in[0];   // (B, C, RH, RW)
    const float* xyz       = (const float*)d_in[1];   // (B, 3, RH, RW)
    float* out = (float*)d_out;                       // (B, C, D, W, H)

    static int* winner_ptr = nullptr;
    if (!winner_ptr) cudaGetSymbolAddress((void**)&winner_ptr, g_winner);

    // 1) winner map := -1 (0xFF bytes)
    cudaMemsetAsync(winner_ptr, 0xFF, sizeof(int) * (size_t)BB * DWH);

    // 2) resolve winners
    scatter_winner_kernel<<<(BB * NN + 255) / 256, 256>>>(xyz);

    // 3) transpose features to (B, N, C)
    {
        dim3 grid(NN / 32, CC / 32, BB);   // (4096, 2, 2)
        dim3 block(32, 8);
        transpose_kernel<<<grid, block>>>(range_res);
    }

    // 4) write BEV output
    {
        dim3 grid((NG + 127) / 128, 4, BB);   // (1375, 4, 2)
        write_bev_kernel<<<grid, 128>>>(out);
    }
}

// round 5
// speedup vs baseline: 1.9227x; 1.0364x over previous
#include <cuda_runtime.h>

// Problem constants (validated rel_err=0.0): W=400, H=352, D=5
#define BB 2
#define CC 64
#define NN (64 * 2048)      // RH*RW = 131072 points per batch
#define WW 400
#define HH 352
#define DD 5
#define DWH (DD * WW * HH)  // 704000 cells per batch
#define NG  (DWH / 4)       // 176000 cell-groups (4 cells each) per batch

#define SCATTER_BLOCKS 1024                 // BB*NN / 256
#define TRANSP_BLOCKS  (4096 * 2 * 2)       // (NN/32) * (CC/32) * BB

// Scratch
__device__ int   g_winner[BB * DWH];               // winner point idx per cell, -1 = empty
__device__ float g_feat_t[(size_t)BB * NN * CC];   // transposed features (B, N, C)

// ---------------------------------------------------------------------------
// Fused pass: scatter-winner blocks + transpose blocks in ONE kernel
// (independent inputs -> run concurrently without multi-stream capture risk)
// ---------------------------------------------------------------------------
__global__ void __launch_bounds__(256) fused_scatter_transpose_kernel(
        const float* __restrict__ xyz, const float* __restrict__ feat) {
    __shared__ float tile[32][33];

    if (blockIdx.x < SCATTER_BLOCKS) {
        // ---- scatter: resolve winners (last point index wins = XLA order) ----
        int t = blockIdx.x * 256 + threadIdx.x;
        int b = t >> 17;          // NN = 2^17
        int n = t & (NN - 1);

        const float xp = xyz[(b * 3 + 0) * NN + n];
        const float yp = xyz[(b * 3 + 1) * NN + n];
        const float zp = xyz[(b * 3 + 2) * NN + n];

        if (!(zp >= -3.0f && zp < 1.0f)) return;
        int zbin = (int)floorf(__fdiv_rn(zp + 3.0f, 0.8f));
        if (zbin < 0 || zbin >= DD) return;

        int xi = (int)__fdiv_rn(-yp, 0.2f) + 200;   // x_img
        xi = min(max(xi, 0), WW - 1);
        int yi = (int)__fdiv_rn(-xp, 0.2f) + 352;   // y_img
        yi = min(max(yi, 0), HH - 1);

        int cell = (zbin * WW + (WW - 1 - xi)) * HH + (HH - 1 - yi);
        atomicMax(&g_winner[b * DWH + cell], n);
    } else {
        // ---- transpose: (B, C, N) -> (B, N, C), 32x32 smem tiles ----
        int bid  = blockIdx.x - SCATTER_BLOCKS;     // [0, 16384)
        int b    = bid >> 13;                       // 2 batches
        int rest = bid & 8191;
        int cblk = rest >> 12;                      // 2 channel blocks
        int nblk = rest & 4095;                     // 4096 n blocks
        const int c0 = cblk * 32;
        const int n0 = nblk * 32;
        const int tx = threadIdx.x & 31;
        const int ty = threadIdx.x >> 5;            // 0..7

        const float* src = feat + ((size_t)b * CC + c0) * NN + n0;
        #pragma unroll
        for (int j = 0; j < 4; j++)
            tile[ty + j * 8][tx] = src[(size_t)(ty + j * 8) * NN + tx];
        __syncthreads();

        float* dst = g_feat_t + ((size_t)b * NN + n0) * CC + c0;
        #pragma unroll
        for (int j = 0; j < 4; j++)
            dst[(size_t)(ty + j * 8) * CC + tx] = tile[tx][ty + j * 8];
    }
}

// ---------------------------------------------------------------------------
// Writer. Thread = (4 consecutive cells, 16 channels).
//  - winner int4 loaded once per thread (coalesced)
//  - gathers: 4 x 64B dense rows from g_feat_t (100% sector utilization)
//  - stores: 16 float4 via __stcs (evict-first: protect g_feat_t in L2)
// ---------------------------------------------------------------------------
__device__ __forceinline__ float f4c(const float4& f, int k) {
    return k == 0 ? f.x : k == 1 ? f.y : k == 2 ? f.z : f.w;
}

__global__ void __launch_bounds__(256) write_bev_kernel(float* __restrict__ out) {
    const int g = blockIdx.x * 256 + threadIdx.x;   // cell-group
    if (g >= NG) return;
    const int cg = blockIdx.y;                      // channels cg*16 .. cg*16+15
    const int b  = blockIdx.z;
    const int cell0 = g * 4;

    const int4 w = *reinterpret_cast<const int4*>(&g_winner[b * DWH + cell0]);
    const int ws[4] = {w.x, w.y, w.z, w.w};

    const float* fb = g_feat_t + (size_t)b * NN * CC + cg * 16;

    float4 v[4][4];   // [cell-in-group][channel quad]
    #pragma unroll
    for (int i = 0; i < 4; i++) {
        if (ws[i] >= 0) {
            const float4* src = reinterpret_cast<const float4*>(fb + (size_t)ws[i] * CC);
            v[i][0] = __ldg(src + 0);
            v[i][1] = __ldg(src + 1);
            v[i][2] = __ldg(src + 2);
            v[i][3] = __ldg(src + 3);
        } else {
            v[i][0] = v[i][1] = v[i][2] = v[i][3] = make_float4(0.f, 0.f, 0.f, 0.f);
        }
    }

    float* ob = out + ((size_t)b * CC + cg * 16) * DWH + cell0;
    #pragma unroll
    for (int c = 0; c < 16; c++) {
        const int q = c >> 2, k = c & 3;
        float4 r;
        r.x = f4c(v[0][q], k);
        r.y = f4c(v[1][q], k);
        r.z = f4c(v[2][q], k);
        r.w = f4c(v[3][q], k);
        __stcs(reinterpret_cast<float4*>(ob + (size_t)c * DWH), r);
    }
}

extern "C" void kernel_launch(void* const* d_in, const int* in_sizes, int n_in,
                              void* d_out, int out_size) {
    const float* range_res = (const float*)d_in[0];   // (B, C, RH, RW)
    const float* xyz       = (const float*)d_in[1];   // (B, 3, RH, RW)
    float* out = (float*)d_out;                       // (B, C, D, W, H)

    static int* winner_ptr = nullptr;
    if (!winner_ptr) cudaGetSymbolAddress((void**)&winner_ptr, g_winner);

    // 1) winner map := -1 (0xFF bytes)
    cudaMemsetAsync(winner_ptr, 0xFF, sizeof(int) * (size_t)BB * DWH);

    // 2) fused scatter + transpose (independent work, one kernel)
    fused_scatter_transpose_kernel<<<SCATTER_BLOCKS + TRANSP_BLOCKS, 256>>>(
        xyz, range_res);

    // 3) write BEV output
    {
        dim3 grid((NG + 255) / 256, 4, BB);   // (688, 4, 2)
        write_bev_kernel<<<grid, 256>>>(out);
    }
}

// round 6
// speedup vs baseline: 1.9253x; 1.0014x over previous
#include <cuda_runtime.h>

// Problem constants (validated rel_err=0.0): W=400, H=352, D=5
#define BB 2
#define CC 64
#define NN (64 * 2048)      // RH*RW = 131072 points per batch
#define WW 400
#define HH 352
#define DD 5
#define DWH (DD * WW * HH)  // 704000 cells per batch
#define NG  (DWH / 4)       // 176000 cell-groups (4 cells each) per batch

#define SCATTER_BLOCKS 1024                 // BB*NN / 256
#define TRANSP_BLOCKS  (4096 * 2 * 2)       // (NN/32) * (CC/32) * BB

// Scratch
__device__ int   g_winner[BB * DWH];               // winner point idx per cell, -1 = empty
__device__ float g_feat_t[(size_t)BB * NN * CC];   // transposed features (B, N, C)

// ---------------------------------------------------------------------------
// Fused pass: scatter-winner blocks + vectorized transpose blocks, ONE kernel
// ---------------------------------------------------------------------------
__global__ void __launch_bounds__(256) fused_scatter_transpose_kernel(
        const float* __restrict__ xyz, const float* __restrict__ feat) {
    __shared__ float tile[32][33];

    if (blockIdx.x < SCATTER_BLOCKS) {
        // ---- scatter: resolve winners (last point index wins = XLA order) ----
        int t = blockIdx.x * 256 + threadIdx.x;
        int b = t >> 17;          // NN = 2^17
        int n = t & (NN - 1);

        const float xp = xyz[(b * 3 + 0) * NN + n];
        const float yp = xyz[(b * 3 + 1) * NN + n];
        const float zp = xyz[(b * 3 + 2) * NN + n];

        if (!(zp >= -3.0f && zp < 1.0f)) return;
        int zbin = (int)floorf(__fdiv_rn(zp + 3.0f, 0.8f));
        if (zbin < 0 || zbin >= DD) return;

        int xi = (int)__fdiv_rn(-yp, 0.2f) + 200;   // x_img
        xi = min(max(xi, 0), WW - 1);
        int yi = (int)__fdiv_rn(-xp, 0.2f) + 352;   // y_img
        yi = min(max(yi, 0), HH - 1);

        int cell = (zbin * WW + (WW - 1 - xi)) * HH + (HH - 1 - yi);
        atomicMax(&g_winner[b * DWH + cell], n);
    } else {
        // ---- transpose: (B, C, N) -> (B, N, C), float4 both gmem sides ----
        int bid  = blockIdx.x - SCATTER_BLOCKS;     // [0, 16384)
        int b    = bid >> 13;
        int rest = bid & 8191;
        int cblk = rest >> 12;                      // 2 channel blocks
        int nblk = rest & 4095;                     // 4096 n blocks
        const int c0 = cblk * 32;
        const int n0 = nblk * 32;

        // load: thread -> (c_row, n4): one float4 along n
        {
            const int c_row = threadIdx.x >> 3;     // 0..31
            const int n4    = threadIdx.x & 7;      // 0..7
            const float4 v = *reinterpret_cast<const float4*>(
                feat + ((size_t)b * CC + c0 + c_row) * NN + n0 + n4 * 4);
            tile[c_row][n4 * 4 + 0] = v.x;
            tile[c_row][n4 * 4 + 1] = v.y;
            tile[c_row][n4 * 4 + 2] = v.z;
            tile[c_row][n4 * 4 + 3] = v.w;
        }
        __syncthreads();

        // store: thread -> (n_row, c4): one float4 along c (conflict-free:
        // banks = 4*c4 + n_row mod 4 pattern covers 0..31 uniquely per warp)
        {
            const int n_row = threadIdx.x >> 3;     // 0..31
            const int c4    = threadIdx.x & 7;      // 0..7
            float4 v;
            v.x = tile[c4 * 4 + 0][n_row];
            v.y = tile[c4 * 4 + 1][n_row];
            v.z = tile[c4 * 4 + 2][n_row];
            v.w = tile[c4 * 4 + 3][n_row];
            *reinterpret_cast<float4*>(
                g_feat_t + ((size_t)b * NN + n0 + n_row) * CC + c0 + c4 * 4) = v;
        }
    }
}

// ---------------------------------------------------------------------------
// Writer. Thread = (4 consecutive cells, 16 channels), streamed per quad:
// 4 independent float4 gathers in flight, then 4 float4 stores — shorter
// front LDG batch (less cross-CTA L1tex queue spread) with enough MLP.
// ---------------------------------------------------------------------------
__device__ __forceinline__ float f4c(const float4& f, int k) {
    return k == 0 ? f.x : k == 1 ? f.y : k == 2 ? f.z : f.w;
}

__global__ void __launch_bounds__(512) write_bev_kernel(float* __restrict__ out) {
    const int g = blockIdx.x * 512 + threadIdx.x;   // cell-group
    if (g >= NG) return;
    const int cg = blockIdx.y;                      // channels cg*16 .. cg*16+15
    const int b  = blockIdx.z;
    const int cell0 = g * 4;

    const int4 w = *reinterpret_cast<const int4*>(&g_winner[b * DWH + cell0]);
    const int ws[4] = {w.x, w.y, w.z, w.w};

    const float* fb = g_feat_t + (size_t)b * NN * CC + cg * 16;
    float* ob = out + ((size_t)b * CC + cg * 16) * DWH + cell0;

    #pragma unroll
    for (int q = 0; q < 4; q++) {
        float4 v[4];
        #pragma unroll
        for (int i = 0; i < 4; i++) {
            v[i] = (ws[i] >= 0)
                 ? __ldg(reinterpret_cast<const float4*>(fb + (size_t)ws[i] * CC) + q)
                 : make_float4(0.f, 0.f, 0.f, 0.f);
        }
        #pragma unroll
        for (int k = 0; k < 4; k++) {
            float4 r;
            r.x = f4c(v[0], k);
            r.y = f4c(v[1], k);
            r.z = f4c(v[2], k);
            r.w = f4c(v[3], k);
            __stcs(reinterpret_cast<float4*>(ob + (size_t)(q * 4 + k) * DWH), r);
        }
    }
}

extern "C" void kernel_launch(void* const* d_in, const int* in_sizes, int n_in,
                              void* d_out, int out_size) {
    const float* range_res = (const float*)d_in[0];   // (B, C, RH, RW)
    const float* xyz       = (const float*)d_in[1];   // (B, 3, RH, RW)
    float* out = (float*)d_out;                       // (B, C, D, W, H)

    static int* winner_ptr = nullptr;
    if (!winner_ptr) cudaGetSymbolAddress((void**)&winner_ptr, g_winner);

    // 1) winner map := -1 (0xFF bytes)
    cudaMemsetAsync(winner_ptr, 0xFF, sizeof(int) * (size_t)BB * DWH);

    // 2) fused scatter + transpose
    fused_scatter_transpose_kernel<<<SCATTER_BLOCKS + TRANSP_BLOCKS, 256>>>(
        xyz, range_res);

    // 3) write BEV output
    {
        dim3 grid((NG + 511) / 512, 4, BB);   // (344, 4, 2)
        write_bev_kernel<<<grid, 512>>>(out);
    }
}